// round 1
// baseline (speedup 1.0000x reference)
#include <cuda_runtime.h>

// FlowNet2 Resample2d (kernel_size=1) bilinear warp.
// input1: [B, C, H, W] float, input2 (flow): [B, 2, H, W] float
// out[b,c,y,x] = bilinear(input1[b,c], x + flow[b,0,y,x], y + flow[b,1,y,x])
// Border-clamped indices, weights from unclamped fractional coords.

#define BB 8
#define CC 32
#define HH 512
#define WW 512
#define HWSZ (HH * WW)

__global__ __launch_bounds__(256)
void resample2d_kernel(const float* __restrict__ in1,
                       const float* __restrict__ flow,
                       float* __restrict__ out) {
    int pix = blockIdx.x * blockDim.x + threadIdx.x;
    if (pix >= BB * HWSZ) return;

    int b  = pix / HWSZ;
    int hw = pix - b * HWSZ;
    int h  = hw / WW;
    int w  = hw - h * WW;

    const float* fl = flow + (size_t)b * 2 * HWSZ;
    float dx = __ldg(fl + hw);
    float dy = __ldg(fl + HWSZ + hw);

    float xf = (float)w + dx;
    float yf = (float)h + dy;
    float x0 = floorf(xf);
    float y0 = floorf(yf);
    float alpha = xf - x0;   // unclamped fractional weights
    float beta  = yf - y0;

    int ix0 = (int)x0;
    int iy0 = (int)y0;
    int xL = min(max(ix0,     0), WW - 1);
    int xR = min(max(ix0 + 1, 0), WW - 1);
    int yT = min(max(iy0,     0), HH - 1);
    int yB = min(max(iy0 + 1, 0), HH - 1);

    float wTL = (1.0f - alpha) * (1.0f - beta);
    float wTR = alpha * (1.0f - beta);
    float wBL = (1.0f - alpha) * beta;
    float wBR = alpha * beta;

    int iTL = yT * WW + xL;
    int iTR = yT * WW + xR;
    int iBL = yB * WW + xL;
    int iBR = yB * WW + xR;

    const float* base = in1 + (size_t)b * CC * HWSZ;
    float*      obase = out + (size_t)b * CC * HWSZ + hw;

    #pragma unroll 8
    for (int c = 0; c < CC; c++) {
        const float* p = base + (size_t)c * HWSZ;
        float v = wTL * __ldg(p + iTL)
                + wTR * __ldg(p + iTR)
                + wBL * __ldg(p + iBL)
                + wBR * __ldg(p + iBR);
        obase[(size_t)c * HWSZ] = v;
    }
}

extern "C" void kernel_launch(void* const* d_in, const int* in_sizes, int n_in,
                              void* d_out, int out_size) {
    const float* input1 = (const float*)d_in[0];
    const float* input2 = (const float*)d_in[1];
    float* out = (float*)d_out;

    const int total_pix = BB * HWSZ;               // 2,097,152
    const int threads = 256;
    const int blocks = (total_pix + threads - 1) / threads;  // 8192
    resample2d_kernel<<<blocks, threads>>>(input1, input2, out);
}

// round 2
// speedup vs baseline: 1.0408x; 1.0408x over previous
#include <cuda_runtime.h>

// FlowNet2 Resample2d (kernel_size=1) bilinear warp.
// input1: [B, C, H, W] float, input2 (flow): [B, 2, H, W] float
// out[b,c,y,x] = bilinear(input1[b,c], x + flow[b,0,y,x], y + flow[b,1,y,x])
// Border-clamped indices, weights from unclamped fractional coords.
//
// L1tex-wavefront-bound kernel: the goal is max occupancy (2048 thr/SM via
// 32-reg budget) to saturate the L1 pipe, with all index math in 32-bit
// shifts/masks (B=8, C=32, H=W=512 are powers of two).

#define BB 8
#define CC 32
#define HH 512
#define WW 512
#define HWSZ (HH * WW)   // 262144 = 2^18

__global__ __launch_bounds__(256, 8)
void resample2d_kernel(const float* __restrict__ in1,
                       const float* __restrict__ flow,
                       float* __restrict__ out) {
    int pix = blockIdx.x * 256 + threadIdx.x;   // grid sized exactly; no bounds check

    int b  = pix >> 18;            // / HWSZ
    int hw = pix & (HWSZ - 1);
    int h  = hw >> 9;              // / WW
    int w  = hw & (WW - 1);

    const float* fl = flow + ((size_t)b << 19); // b * 2 * HWSZ
    float dx = __ldg(fl + hw);
    float dy = __ldg(fl + HWSZ + hw);

    float xf = (float)w + dx;
    float yf = (float)h + dy;
    float x0 = floorf(xf);
    float y0 = floorf(yf);
    float alpha = xf - x0;   // unclamped fractional weights
    float beta  = yf - y0;

    int ix0 = (int)x0;
    int iy0 = (int)y0;
    int xL = min(max(ix0,     0), WW - 1);
    int xR = min(max(ix0 + 1, 0), WW - 1);
    int yT = min(max(iy0,     0), HH - 1);
    int yB = min(max(iy0 + 1, 0), HH - 1);

    float wTR = alpha * (1.0f - beta);
    float wBL = (1.0f - alpha) * beta;
    float wBR = alpha * beta;
    float wTL = 1.0f - wTR - wBL - wBR;  // == (1-a)(1-b); saves a reg chain

    int rT = yT << 9;
    int rB = yB << 9;

    const float* base = in1 + ((size_t)b << 23);       // b * C * HWSZ
    const float* pTL = base + (rT + xL);
    const float* pTR = base + (rT + xR);
    const float* pBL = base + (rB + xL);
    const float* pBR = base + (rB + xR);
    float* op = out + ((size_t)b << 23) + hw;

    #pragma unroll 4
    for (int c = 0; c < CC; c++) {
        int off = c << 18;   // c * HWSZ (fits easily in int)
        float v = wTL * __ldg(pTL + off)
                + wTR * __ldg(pTR + off)
                + wBL * __ldg(pBL + off)
                + wBR * __ldg(pBR + off);
        op[off] = v;
    }
}

extern "C" void kernel_launch(void* const* d_in, const int* in_sizes, int n_in,
                              void* d_out, int out_size) {
    const float* input1 = (const float*)d_in[0];
    const float* input2 = (const float*)d_in[1];
    float* out = (float*)d_out;

    const int total_pix = BB * HWSZ;               // 2,097,152
    const int threads = 256;
    const int blocks = total_pix / threads;        // 8192 (exact)
    resample2d_kernel<<<blocks, threads>>>(input1, input2, out);
}